// round 7
// baseline (speedup 1.0000x reference)
#include <cuda_runtime.h>

// Problem dims (fixed by the dataset)
#define Bn 8
#define Cn 19
#define Hn 384
#define Wn 384
#define NPIX (Bn * Hn * Wn)
#define HWn (Hn * Wn)
#define BOUND 777  // B + C + H + W = 8+1+384+384
#define DT_THREADS 256
#define DT_BLOCKS ((NPIX / 16) / DT_THREADS)   // 288

// Scratch (allocation-free rule: __device__ globals), 16B-aligned for uint4 IO
__device__ __align__(16) unsigned char g_pred[NPIX];
__device__ __align__(16) unsigned char g_tb[NPIX];    // target-border bitmap (0/1)
__device__ float        g_ce;      // zero-init at load; last dt block resets it
__device__ unsigned int g_border;  // ditto
__device__ unsigned int g_cnt;     // ditto

// ---------------------------------------------------------------------------
// Kernel 1: fused CE(sum, ignore=255) + argmax(pred map) + TARGET BORDER map.
// 4 pixels/thread via float4/int4; 19 channel float4s in registers (max pass,
// then independent exp sum -> no serial MUFU chain). Rides the HBM roofline.
// border(i,j) = ((t[i+1,j]-t[i,j]) + (t[i,j+1]-t[i,j])) != 0, zero-padded.
// ---------------------------------------------------------------------------
__global__ void __launch_bounds__(256) ce_kernel(
    const float* __restrict__ x, const int* __restrict__ tgt) {
    int idx4 = blockIdx.x * blockDim.x + threadIdx.x;  // 0 .. NPIX/4-1
    const int HW4 = HWn / 4;
    int b = idx4 / HW4;
    int hw4 = idx4 - b * HW4;
    const float4* p = (const float4*)(x + (size_t)b * Cn * HWn) + hw4;

    float v[Cn][4];
    #pragma unroll
    for (int c = 0; c < Cn; c++) {
        float4 q = __ldg(p + (size_t)c * HW4);
        v[c][0] = q.x; v[c][1] = q.y; v[c][2] = q.z; v[c][3] = q.w;
    }

    int hw = hw4 * 4;
    int i = hw / Wn;                 // row (4 pixels always within one row)
    int j0 = hw - i * Wn;            // col of pixel 0
    int gbase = b * HWn + hw;        // global pixel index of pixel 0

    int4 tq = __ldg((const int4*)tgt + idx4);
    int t[5];
    t[0] = tq.x; t[1] = tq.y; t[2] = tq.z; t[3] = tq.w;
    t[4] = (j0 + 4 < Wn) ? __ldg(tgt + gbase + 4) : t[3];   // row-end pad

    int td[4];
    if (i < Hn - 1) {
        int4 dq = __ldg((const int4*)tgt + idx4 + Wn / 4);
        td[0] = dq.x; td[1] = dq.y; td[2] = dq.z; td[3] = dq.w;
    } else {
        td[0] = t[0]; td[1] = t[1]; td[2] = t[2]; td[3] = t[3];  // bottom pad
    }

    float nll = 0.0f;
    unsigned int packed_pred = 0, packed_border = 0;
    #pragma unroll
    for (int k = 0; k < 4; k++) {
        float m = v[0][k];
        int arg = 0;
        float tv = v[0][k];
        #pragma unroll
        for (int c = 1; c < Cn; c++) {
            float vc = v[c][k];
            if (vc > m) { m = vc; arg = c; }     // first-max tie break
            tv = (c == t[k]) ? vc : tv;           // register-resident gather
        }
        packed_pred |= ((unsigned int)arg) << (8 * k);

        int bd = (((td[k] - t[k]) + (t[k + 1] - t[k])) != 0) ? 1 : 0;
        packed_border |= ((unsigned int)bd) << (8 * k);

        float s = 0.0f;
        #pragma unroll
        for (int c = 0; c < Cn; c++) s += __expf(v[c][k] - m);

        if (t[k] != 255) nll += (m + __logf(s)) - tv;
    }
    ((unsigned int*)g_pred)[idx4] = packed_pred;
    ((unsigned int*)g_tb)[idx4]   = packed_border;

    // block reduction -> atomicAdd
    #pragma unroll
    for (int o = 16; o > 0; o >>= 1)
        nll += __shfl_down_sync(0xFFFFFFFFu, nll, o);
    __shared__ float ws[8];
    int lane = threadIdx.x & 31, wid = threadIdx.x >> 5;
    if (lane == 0) ws[wid] = nll;
    __syncthreads();
    if (wid == 0) {
        float v2 = (lane < (blockDim.x >> 5)) ? ws[lane] : 0.0f;
        #pragma unroll
        for (int o = 4; o > 0; o >>= 1)
            v2 += __shfl_down_sync(0xFFFFFFFFu, v2, o);
        if (lane == 0) atomicAdd(&g_ce, v2);
    }
}

// ---------------------------------------------------------------------------
// Kernel 2: border loss, NO shared tiles. Each thread scans 16 pixels via one
// uint4 of the target-border map; bytes==1 (the overwhelming case) -> d=0 ->
// contributes nothing. Rare pixels: pred-border test (L2-hot loads) + exact
// expanding-ring search on the global border map (expected d=1, ~8 reads).
// LAST BLOCK finalizes out = g_ce + 0.2*border and resets accumulators.
// ---------------------------------------------------------------------------
__global__ void __launch_bounds__(DT_THREADS) dt_kernel(float* __restrict__ out) {
    __shared__ int wsum[DT_THREADS / 32];

    int idx16 = blockIdx.x * blockDim.x + threadIdx.x;   // 0 .. NPIX/16-1
    uint4 w = __ldg((const uint4*)g_tb + idx16);

    int contrib = 0;
    const unsigned int ONES = 0x01010101u;
    if (!(w.x == ONES && w.y == ONES && w.z == ONES && w.w == ONES)) {
        unsigned int words[4] = {w.x, w.y, w.z, w.w};
        int pix0 = idx16 * 16;
        int b = pix0 / HWn;
        const unsigned char* tb = g_tb + b * HWn;
        int hw0 = pix0 - b * HWn;            // 16 pixels stay within one row
        int gi = hw0 / Wn;
        int gj0 = hw0 - gi * Wn;

        #pragma unroll
        for (int wk = 0; wk < 4; wk++) {
            unsigned int cw = words[wk];
            if (cw == ONES) continue;
            #pragma unroll
            for (int k = 0; k < 4; k++) {
                if (((cw >> (8 * k)) & 0xFFu) != 0u) continue;  // d=0 -> adds 0
                int gj = gj0 + wk * 4 + k;
                int pix = pix0 + wk * 4 + k;

                // pred border at (gi, gj) — L2-hot scalar loads
                int p0 = g_pred[pix];
                int pr = (gj < Wn - 1) ? (int)g_pred[pix + 1]  : p0;
                int pd = (gi < Hn - 1) ? (int)g_pred[pix + Wn] : p0;
                if (((pd - p0) + (pr - p0)) == 0) continue;

                // exact expanding-ring Chebyshev search on global border map
                int d = BOUND;
                for (int tt = 1; tt <= Hn + Wn; tt++) {
                    bool g = false;
                    int ra = gi - tt, rb = gi + tt;
                    int ca = gj - tt, cb = gj + tt;
                    int cl = ca > 0 ? ca : 0;
                    int cr = cb < Wn - 1 ? cb : Wn - 1;
                    if (ra >= 0) for (int c = cl; c <= cr; c++) g |= tb[ra * Wn + c] != 0;
                    if (rb < Hn) for (int c = cl; c <= cr; c++) g |= tb[rb * Wn + c] != 0;
                    int rl = (ra + 1) > 0 ? (ra + 1) : 0;
                    int rh = (rb - 1) < Hn - 1 ? (rb - 1) : Hn - 1;
                    if (ca >= 0) for (int r = rl; r <= rh; r++) g |= tb[r * Wn + ca] != 0;
                    if (cb < Wn) for (int r = rl; r <= rh; r++) g |= tb[r * Wn + cb] != 0;
                    if (g) { d = tt; break; }
                    if (ra < 0 && rb >= Hn && ca < 0 && cb >= Wn) break;  // no border at all
                }
                contrib += d;
            }
        }
    }

    // integer block reduction (exact) -> u32 atomic
    #pragma unroll
    for (int o = 16; o > 0; o >>= 1)
        contrib += __shfl_down_sync(0xFFFFFFFFu, contrib, o);
    int lane = threadIdx.x & 31, wid = threadIdx.x >> 5;
    if (lane == 0) wsum[wid] = contrib;
    __syncthreads();
    if (wid == 0) {
        int v2 = (lane < (DT_THREADS / 32)) ? wsum[lane] : 0;
        #pragma unroll
        for (int o = 4; o > 0; o >>= 1)
            v2 += __shfl_down_sync(0xFFFFFFFFu, v2, o);
        if (lane == 0) {
            atomicAdd(&g_border, (unsigned int)v2);
            __threadfence();
            unsigned int done = atomicAdd(&g_cnt, 1u);
            if (done == DT_BLOCKS - 1) {       // last block: finalize + reset
                __threadfence();
                out[0] = g_ce + 0.2f * (float)g_border;
                g_ce = 0.0f;
                g_border = 0u;
                g_cnt = 0u;
            }
        }
    }
}

extern "C" void kernel_launch(void* const* d_in, const int* in_sizes, int n_in,
                              void* d_out, int out_size) {
    const float* slices  = (const float*)d_in[0];
    const int*   targets = (const int*)d_in[1];   // JAX int64 -> int32 (x64 disabled)
    float* out = (float*)d_out;

    ce_kernel<<<(NPIX / 4) / 256, 256>>>(slices, targets);
    dt_kernel<<<DT_BLOCKS, DT_THREADS>>>(out);
}

// round 8
// speedup vs baseline: 2.4413x; 2.4413x over previous
#include <cuda_runtime.h>

// Problem dims (fixed by the dataset)
#define Bn 8
#define Cn 19
#define Hn 384
#define Wn 384
#define NPIX (Bn * Hn * Wn)
#define HWn (Hn * Wn)
#define BOUND 777  // B + C + H + W = 8+1+384+384
#define DT_GRID 148
#define DT_THREADS 256

// Scratch (allocation-free rule: __device__ globals), 16B-aligned for uint4 IO
__device__ __align__(16) unsigned char g_pred[NPIX];
__device__ __align__(16) unsigned char g_tb[NPIX];    // target-border bitmap (0/1)
__device__ int          g_rare[NPIX];  // pixels with tb==0 (candidates, ~0.3%)
__device__ float        g_ce;          // zero-init at load; last dt block resets
__device__ unsigned int g_border;      // ditto
__device__ unsigned int g_cnt;         // ditto
__device__ unsigned int g_nrare;       // ditto

// ---------------------------------------------------------------------------
// Kernel 1: fused CE(sum, ignore=255) + argmax(pred map) + target-border map
// + COMPACTION of rare pixels (tb==0) into g_rare.
// 4 pixels/thread via float4/int4; 19 channel float4s in registers (max pass,
// then independent exp sum -> no serial MUFU chain). Rides the HBM roofline.
// border(i,j) = ((t[i+1,j]-t[i,j]) + (t[i,j+1]-t[i,j])) != 0, zero-padded.
// ---------------------------------------------------------------------------
__global__ void __launch_bounds__(256) ce_kernel(
    const float* __restrict__ x, const int* __restrict__ tgt) {
    int idx4 = blockIdx.x * blockDim.x + threadIdx.x;  // 0 .. NPIX/4-1
    const int HW4 = HWn / 4;
    int b = idx4 / HW4;
    int hw4 = idx4 - b * HW4;
    const float4* p = (const float4*)(x + (size_t)b * Cn * HWn) + hw4;

    float v[Cn][4];
    #pragma unroll
    for (int c = 0; c < Cn; c++) {
        float4 q = __ldg(p + (size_t)c * HW4);
        v[c][0] = q.x; v[c][1] = q.y; v[c][2] = q.z; v[c][3] = q.w;
    }

    int hw = hw4 * 4;
    int i = hw / Wn;                 // row (4 pixels always within one row)
    int j0 = hw - i * Wn;            // col of pixel 0
    int gbase = b * HWn + hw;        // global pixel index of pixel 0

    int4 tq = __ldg((const int4*)tgt + idx4);
    int t[5];
    t[0] = tq.x; t[1] = tq.y; t[2] = tq.z; t[3] = tq.w;
    t[4] = (j0 + 4 < Wn) ? __ldg(tgt + gbase + 4) : t[3];   // row-end pad

    int td[4];
    if (i < Hn - 1) {
        int4 dq = __ldg((const int4*)tgt + idx4 + Wn / 4);
        td[0] = dq.x; td[1] = dq.y; td[2] = dq.z; td[3] = dq.w;
    } else {
        td[0] = t[0]; td[1] = t[1]; td[2] = t[2]; td[3] = t[3];  // bottom pad
    }

    float nll = 0.0f;
    unsigned int packed_pred = 0, packed_border = 0;
    #pragma unroll
    for (int k = 0; k < 4; k++) {
        float m = v[0][k];
        int arg = 0;
        float tv = v[0][k];
        #pragma unroll
        for (int c = 1; c < Cn; c++) {
            float vc = v[c][k];
            if (vc > m) { m = vc; arg = c; }     // first-max tie break
            tv = (c == t[k]) ? vc : tv;           // register-resident gather
        }
        packed_pred |= ((unsigned int)arg) << (8 * k);

        int bd = (((td[k] - t[k]) + (t[k + 1] - t[k])) != 0) ? 1 : 0;
        packed_border |= ((unsigned int)bd) << (8 * k);

        float s = 0.0f;
        #pragma unroll
        for (int c = 0; c < Cn; c++) s += __expf(v[c][k] - m);

        if (t[k] != 255) nll += (m + __logf(s)) - tv;
    }
    ((unsigned int*)g_pred)[idx4] = packed_pred;
    ((unsigned int*)g_tb)[idx4]   = packed_border;

    // Compact rare pixels (tb==0). ~0.3% of pixels -> ~3.5k atomics total.
    if (packed_border != 0x01010101u) {
        #pragma unroll
        for (int k = 0; k < 4; k++) {
            if (((packed_border >> (8 * k)) & 0xFFu) == 0u) {
                unsigned int slot = atomicAdd(&g_nrare, 1u);
                g_rare[slot] = gbase + k;
            }
        }
    }

    // block reduction -> atomicAdd
    #pragma unroll
    for (int o = 16; o > 0; o >>= 1)
        nll += __shfl_down_sync(0xFFFFFFFFu, nll, o);
    __shared__ float ws[8];
    int lane = threadIdx.x & 31, wid = threadIdx.x >> 5;
    if (lane == 0) ws[wid] = nll;
    __syncthreads();
    if (wid == 0) {
        float v2 = (lane < (blockDim.x >> 5)) ? ws[lane] : 0.0f;
        #pragma unroll
        for (int o = 4; o > 0; o >>= 1)
            v2 += __shfl_down_sync(0xFFFFFFFFu, v2, o);
        if (lane == 0) atomicAdd(&g_ce, v2);
    }
}

// ---------------------------------------------------------------------------
// Kernel 2: border loss over the COMPACTED rare-pixel list only (~3.5k px).
// Grid-stride; each pixel: pred-border test (3 L2-hot bytes) + exact
// expanding-ring Chebyshev search (expected d=1 -> 8 byte reads).
// LAST BLOCK finalizes out = g_ce + 0.2*border and resets all accumulators.
// ---------------------------------------------------------------------------
__global__ void __launch_bounds__(DT_THREADS) dt_kernel(float* __restrict__ out) {
    __shared__ int wsum[DT_THREADS / 32];

    int n = (int)g_nrare;
    int contrib = 0;
    for (int it = blockIdx.x * blockDim.x + threadIdx.x; it < n;
         it += gridDim.x * blockDim.x) {
        int pix = g_rare[it];
        int b = pix / HWn;
        int hwv = pix - b * HWn;
        int gi = hwv / Wn;
        int gj = hwv - gi * Wn;
        const unsigned char* tb = g_tb + b * HWn;

        // pred border at (gi, gj) — L2-hot scalar loads
        int p0 = g_pred[pix];
        int pr = (gj < Wn - 1) ? (int)g_pred[pix + 1]  : p0;
        int pd = (gi < Hn - 1) ? (int)g_pred[pix + Wn] : p0;
        if (((pd - p0) + (pr - p0)) == 0) continue;

        // exact expanding-ring Chebyshev search on the border map
        int d = BOUND;
        for (int tt = 1; tt <= Hn + Wn; tt++) {
            bool g = false;
            int ra = gi - tt, rb = gi + tt;
            int ca = gj - tt, cb = gj + tt;
            int cl = ca > 0 ? ca : 0;
            int cr = cb < Wn - 1 ? cb : Wn - 1;
            if (ra >= 0) for (int c = cl; c <= cr; c++) g |= tb[ra * Wn + c] != 0;
            if (rb < Hn) for (int c = cl; c <= cr; c++) g |= tb[rb * Wn + c] != 0;
            int rl = (ra + 1) > 0 ? (ra + 1) : 0;
            int rh = (rb - 1) < Hn - 1 ? (rb - 1) : Hn - 1;
            if (ca >= 0) for (int r = rl; r <= rh; r++) g |= tb[r * Wn + ca] != 0;
            if (cb < Wn) for (int r = rl; r <= rh; r++) g |= tb[r * Wn + cb] != 0;
            if (g) { d = tt; break; }
            if (ra < 0 && rb >= Hn && ca < 0 && cb >= Wn) break;  // no border at all
        }
        contrib += d;
    }

    // integer block reduction (exact) -> u32 atomic
    #pragma unroll
    for (int o = 16; o > 0; o >>= 1)
        contrib += __shfl_down_sync(0xFFFFFFFFu, contrib, o);
    int lane = threadIdx.x & 31, wid = threadIdx.x >> 5;
    if (lane == 0) wsum[wid] = contrib;
    __syncthreads();
    if (wid == 0) {
        int v2 = (lane < (DT_THREADS / 32)) ? wsum[lane] : 0;
        #pragma unroll
        for (int o = 4; o > 0; o >>= 1)
            v2 += __shfl_down_sync(0xFFFFFFFFu, v2, o);
        if (lane == 0) {
            atomicAdd(&g_border, (unsigned int)v2);
            __threadfence();
            unsigned int done = atomicAdd(&g_cnt, 1u);
            if (done == gridDim.x - 1) {       // last block: finalize + reset
                __threadfence();
                out[0] = g_ce + 0.2f * (float)g_border;
                g_ce = 0.0f;
                g_border = 0u;
                g_cnt = 0u;
                g_nrare = 0u;
            }
        }
    }
}

extern "C" void kernel_launch(void* const* d_in, const int* in_sizes, int n_in,
                              void* d_out, int out_size) {
    const float* slices  = (const float*)d_in[0];
    const int*   targets = (const int*)d_in[1];   // JAX int64 -> int32 (x64 disabled)
    float* out = (float*)d_out;

    ce_kernel<<<(NPIX / 4) / 256, 256>>>(slices, targets);
    dt_kernel<<<DT_GRID, DT_THREADS>>>(out);
}

// round 9
// speedup vs baseline: 2.6041x; 1.0667x over previous
#include <cuda_runtime.h>

// Problem dims (fixed by the dataset)
#define Bn 8
#define Cn 19
#define Hn 384
#define Wn 384
#define NPIX (Bn * Hn * Wn)
#define HWn (Hn * Wn)
#define BOUND 777  // B + C + H + W = 8+1+384+384
#define DT_GRID 592
#define DT_THREADS 256

// Scratch (allocation-free rule: __device__ globals), 16B-aligned for uint4 IO
__device__ __align__(16) unsigned char g_pred[NPIX];
__device__ __align__(16) unsigned char g_tb[NPIX];    // target-border bitmap (0/1)
__device__ int          g_rare[NPIX];  // pixels with tb==0 (~2.6% = 31k)
__device__ float        g_ce;          // zero-init at load; last dt block resets
__device__ unsigned int g_border;      // ditto
__device__ unsigned int g_cnt;         // ditto
__device__ unsigned int g_nrare;       // ditto

// ---------------------------------------------------------------------------
// Kernel 1: fused CE(sum, ignore=255) + argmax(pred map) + target-border map
// + COMPACTION of candidate pixels (tb==0) into g_rare.
// 4 pixels/thread via float4/int4; 19 channel float4s in registers (max pass,
// then independent exp sum -> no serial MUFU chain). Rides the HBM roofline.
// border(i,j) = ((t[i+1,j]-t[i,j]) + (t[i,j+1]-t[i,j])) != 0, zero-padded.
// ---------------------------------------------------------------------------
__global__ void __launch_bounds__(256) ce_kernel(
    const float* __restrict__ x, const int* __restrict__ tgt) {
    int idx4 = blockIdx.x * blockDim.x + threadIdx.x;  // 0 .. NPIX/4-1
    const int HW4 = HWn / 4;
    int b = idx4 / HW4;
    int hw4 = idx4 - b * HW4;
    const float4* p = (const float4*)(x + (size_t)b * Cn * HWn) + hw4;

    float v[Cn][4];
    #pragma unroll
    for (int c = 0; c < Cn; c++) {
        float4 q = __ldg(p + (size_t)c * HW4);
        v[c][0] = q.x; v[c][1] = q.y; v[c][2] = q.z; v[c][3] = q.w;
    }

    int hw = hw4 * 4;
    int i = hw / Wn;                 // row (4 pixels always within one row)
    int j0 = hw - i * Wn;            // col of pixel 0
    int gbase = b * HWn + hw;        // global pixel index of pixel 0

    int4 tq = __ldg((const int4*)tgt + idx4);
    int t[5];
    t[0] = tq.x; t[1] = tq.y; t[2] = tq.z; t[3] = tq.w;
    t[4] = (j0 + 4 < Wn) ? __ldg(tgt + gbase + 4) : t[3];   // row-end pad

    int td[4];
    if (i < Hn - 1) {
        int4 dq = __ldg((const int4*)tgt + idx4 + Wn / 4);
        td[0] = dq.x; td[1] = dq.y; td[2] = dq.z; td[3] = dq.w;
    } else {
        td[0] = t[0]; td[1] = t[1]; td[2] = t[2]; td[3] = t[3];  // bottom pad
    }

    float nll = 0.0f;
    unsigned int packed_pred = 0, packed_border = 0;
    #pragma unroll
    for (int k = 0; k < 4; k++) {
        float m = v[0][k];
        int arg = 0;
        float tv = v[0][k];
        #pragma unroll
        for (int c = 1; c < Cn; c++) {
            float vc = v[c][k];
            if (vc > m) { m = vc; arg = c; }     // first-max tie break
            tv = (c == t[k]) ? vc : tv;           // register-resident gather
        }
        packed_pred |= ((unsigned int)arg) << (8 * k);

        int bd = (((td[k] - t[k]) + (t[k + 1] - t[k])) != 0) ? 1 : 0;
        packed_border |= ((unsigned int)bd) << (8 * k);

        float s = 0.0f;
        #pragma unroll
        for (int c = 0; c < Cn; c++) s += __expf(v[c][k] - m);

        if (t[k] != 255) nll += (m + __logf(s)) - tv;
    }
    ((unsigned int*)g_pred)[idx4] = packed_pred;
    ((unsigned int*)g_tb)[idx4]   = packed_border;

    // Compact candidate pixels (tb==0), ~2.6% of all pixels.
    if (packed_border != 0x01010101u) {
        #pragma unroll
        for (int k = 0; k < 4; k++) {
            if (((packed_border >> (8 * k)) & 0xFFu) == 0u) {
                unsigned int slot = atomicAdd(&g_nrare, 1u);
                g_rare[slot] = gbase + k;
            }
        }
    }

    // block reduction -> atomicAdd
    #pragma unroll
    for (int o = 16; o > 0; o >>= 1)
        nll += __shfl_down_sync(0xFFFFFFFFu, nll, o);
    __shared__ float ws[8];
    int lane = threadIdx.x & 31, wid = threadIdx.x >> 5;
    if (lane == 0) ws[wid] = nll;
    __syncthreads();
    if (wid == 0) {
        float v2 = (lane < (blockDim.x >> 5)) ? ws[lane] : 0.0f;
        #pragma unroll
        for (int o = 4; o > 0; o >>= 1)
            v2 += __shfl_down_sync(0xFFFFFFFFu, v2, o);
        if (lane == 0) atomicAdd(&g_ce, v2);
    }
}

// ---------------------------------------------------------------------------
// Kernel 2: border loss over the compacted candidate list (~31k px).
// Branch-free batched loads: 3 pred bytes + 8 ring-1 border bytes issued
// together (clamped addresses, 0/1 validity masks) -> ONE L2 round trip for
// the d=1 case, which is essentially all of them (P(d>=2) ~ 0.026^8).
// Exact expanding-ring fallback from tt=2. LAST BLOCK finalizes + resets.
// ---------------------------------------------------------------------------
__global__ void __launch_bounds__(DT_THREADS) dt_kernel(float* __restrict__ out) {
    __shared__ int wsum[DT_THREADS / 32];

    int n = (int)g_nrare;
    int contrib = 0;
    for (int it = blockIdx.x * blockDim.x + threadIdx.x; it < n;
         it += gridDim.x * blockDim.x) {
        int pix = g_rare[it];
        int b = pix / HWn;
        int hwv = pix - b * HWn;
        int gi = hwv / Wn;
        int gj = hwv - gi * Wn;
        const unsigned char* tb = g_tb + b * HWn;

        int hasU = (gi > 0), hasD = (gi < Hn - 1);
        int hasL = (gj > 0), hasR = (gj < Wn - 1);

        // --- batched independent loads (single round trip) ---
        // pred bytes: clamped offsets; if neighbor absent the diff is 0 anyway.
        int p0 = g_pred[pix];
        int pr = g_pred[pix + hasR];
        int pd = g_pred[pix + hasD * Wn];
        // ring-1 border bytes: clamped addresses + validity masks.
        int cu = hwv - hasU * Wn, cd = hwv + hasD * Wn;
        int f = 0;
        f |= (int)tb[cu - hasL] & (hasU & hasL);
        f |= (int)tb[cu]        &  hasU;
        f |= (int)tb[cu + hasR] & (hasU & hasR);
        f |= (int)tb[hwv - hasL] & hasL;
        f |= (int)tb[hwv + hasR] & hasR;
        f |= (int)tb[cd - hasL] & (hasD & hasL);
        f |= (int)tb[cd]        &  hasD;
        f |= (int)tb[cd + hasR] & (hasD & hasR);

        bool pb = (((pd - p0) + (pr - p0)) != 0);
        if (!pb) continue;

        int d;
        if (f) {
            d = 1;
        } else {
            // exact expanding-ring Chebyshev fallback (essentially never taken)
            d = BOUND;
            for (int tt = 2; tt <= Hn + Wn; tt++) {
                bool g = false;
                int ra = gi - tt, rb = gi + tt;
                int ca = gj - tt, cb = gj + tt;
                int cl = ca > 0 ? ca : 0;
                int cr = cb < Wn - 1 ? cb : Wn - 1;
                if (ra >= 0) for (int c = cl; c <= cr; c++) g |= tb[ra * Wn + c] != 0;
                if (rb < Hn) for (int c = cl; c <= cr; c++) g |= tb[rb * Wn + c] != 0;
                int rl = (ra + 1) > 0 ? (ra + 1) : 0;
                int rh = (rb - 1) < Hn - 1 ? (rb - 1) : Hn - 1;
                if (ca >= 0) for (int r = rl; r <= rh; r++) g |= tb[r * Wn + ca] != 0;
                if (cb < Wn) for (int r = rl; r <= rh; r++) g |= tb[r * Wn + cb] != 0;
                if (g) { d = tt; break; }
                if (ra < 0 && rb >= Hn && ca < 0 && cb >= Wn) break;  // no border at all
            }
        }
        contrib += d;
    }

    // integer block reduction (exact) -> u32 atomic
    #pragma unroll
    for (int o = 16; o > 0; o >>= 1)
        contrib += __shfl_down_sync(0xFFFFFFFFu, contrib, o);
    int lane = threadIdx.x & 31, wid = threadIdx.x >> 5;
    if (lane == 0) wsum[wid] = contrib;
    __syncthreads();
    if (wid == 0) {
        int v2 = (lane < (DT_THREADS / 32)) ? wsum[lane] : 0;
        #pragma unroll
        for (int o = 4; o > 0; o >>= 1)
            v2 += __shfl_down_sync(0xFFFFFFFFu, v2, o);
        if (lane == 0) {
            atomicAdd(&g_border, (unsigned int)v2);
            __threadfence();
            unsigned int done = atomicAdd(&g_cnt, 1u);
            if (done == gridDim.x - 1) {       // last block: finalize + reset
                __threadfence();
                out[0] = g_ce + 0.2f * (float)g_border;
                g_ce = 0.0f;
                g_border = 0u;
                g_cnt = 0u;
                g_nrare = 0u;
            }
        }
    }
}

extern "C" void kernel_launch(void* const* d_in, const int* in_sizes, int n_in,
                              void* d_out, int out_size) {
    const float* slices  = (const float*)d_in[0];
    const int*   targets = (const int*)d_in[1];   // JAX int64 -> int32 (x64 disabled)
    float* out = (float*)d_out;

    ce_kernel<<<(NPIX / 4) / 256, 256>>>(slices, targets);
    dt_kernel<<<DT_GRID, DT_THREADS>>>(out);
}

// round 10
// speedup vs baseline: 3.2058x; 1.2311x over previous
#include <cuda_runtime.h>

// Problem dims (fixed by the dataset)
#define Bn 8
#define Cn 19
#define Hn 384
#define Wn 384
#define NPIX (Bn * Hn * Wn)
#define HWn (Hn * Wn)
#define BOUND 777  // B + C + H + W = 8+1+384+384
#define DT_GRID 592
#define DT_THREADS 256

// Scratch (allocation-free rule: __device__ globals), 16B-aligned for uint4 IO
__device__ __align__(16) unsigned char g_pred[NPIX];
__device__ __align__(16) unsigned char g_tb[NPIX];    // target-border bitmap (0/1)
__device__ int          g_rare[NPIX];  // pixels with tb==0 (~2.6% = 31k)
__device__ float        g_ce;          // zero-init at load; last dt block resets
__device__ unsigned int g_border;      // ditto
__device__ unsigned int g_cnt;         // ditto
__device__ unsigned int g_nrare;       // ditto

// ---------------------------------------------------------------------------
// Kernel 1: fused CE(sum, ignore=255) + argmax(pred map) + target-border map
// + WARP-AGGREGATED compaction of candidate pixels (tb==0) into g_rare.
// 4 pixels/thread via float4/int4; 19 channel float4s in registers (max pass,
// then independent exp sum -> no serial MUFU chain).
// border(i,j) = ((t[i+1,j]-t[i,j]) + (t[i,j+1]-t[i,j])) != 0, zero-padded.
// ---------------------------------------------------------------------------
__global__ void __launch_bounds__(256) ce_kernel(
    const float* __restrict__ x, const int* __restrict__ tgt) {
    int idx4 = blockIdx.x * blockDim.x + threadIdx.x;  // 0 .. NPIX/4-1
    const int HW4 = HWn / 4;
    int b = idx4 / HW4;
    int hw4 = idx4 - b * HW4;
    const float4* p = (const float4*)(x + (size_t)b * Cn * HWn) + hw4;

    float v[Cn][4];
    #pragma unroll
    for (int c = 0; c < Cn; c++) {
        float4 q = __ldg(p + (size_t)c * HW4);
        v[c][0] = q.x; v[c][1] = q.y; v[c][2] = q.z; v[c][3] = q.w;
    }

    int hw = hw4 * 4;
    int i = hw / Wn;                 // row (4 pixels always within one row)
    int j0 = hw - i * Wn;            // col of pixel 0
    int gbase = b * HWn + hw;        // global pixel index of pixel 0

    int4 tq = __ldg((const int4*)tgt + idx4);
    int t[5];
    t[0] = tq.x; t[1] = tq.y; t[2] = tq.z; t[3] = tq.w;
    t[4] = (j0 + 4 < Wn) ? __ldg(tgt + gbase + 4) : t[3];   // row-end pad

    int td[4];
    if (i < Hn - 1) {
        int4 dq = __ldg((const int4*)tgt + idx4 + Wn / 4);
        td[0] = dq.x; td[1] = dq.y; td[2] = dq.z; td[3] = dq.w;
    } else {
        td[0] = t[0]; td[1] = t[1]; td[2] = t[2]; td[3] = t[3];  // bottom pad
    }

    float nll = 0.0f;
    unsigned int packed_pred = 0, packed_border = 0;
    #pragma unroll
    for (int k = 0; k < 4; k++) {
        float m = v[0][k];
        int arg = 0;
        float tv = v[0][k];
        #pragma unroll
        for (int c = 1; c < Cn; c++) {
            float vc = v[c][k];
            if (vc > m) { m = vc; arg = c; }     // first-max tie break
            tv = (c == t[k]) ? vc : tv;           // register-resident gather
        }
        packed_pred |= ((unsigned int)arg) << (8 * k);

        int bd = (((td[k] - t[k]) + (t[k + 1] - t[k])) != 0) ? 1 : 0;
        packed_border |= ((unsigned int)bd) << (8 * k);

        float s = 0.0f;
        #pragma unroll
        for (int c = 0; c < Cn; c++) s += __expf(v[c][k] - m);

        if (t[k] != 255) nll += (m + __logf(s)) - tv;
    }
    ((unsigned int*)g_pred)[idx4] = packed_pred;
    ((unsigned int*)g_tb)[idx4]   = packed_border;

    int lane = threadIdx.x & 31, wid = threadIdx.x >> 5;

    // Warp-aggregated compaction of candidate pixels (tb byte == 0).
    {
        int nr = 0;
        #pragma unroll
        for (int k = 0; k < 4; k++)
            nr += (((packed_border >> (8 * k)) & 0xFFu) == 0u);

        // inclusive warp scan of nr
        int scan = nr;
        #pragma unroll
        for (int o = 1; o < 32; o <<= 1) {
            int sv = __shfl_up_sync(0xFFFFFFFFu, scan, o);
            if (lane >= o) scan += sv;
        }
        int total = __shfl_sync(0xFFFFFFFFu, scan, 31);
        if (total > 0) {
            unsigned int base = 0;
            if (lane == 31) base = atomicAdd(&g_nrare, (unsigned int)total);
            base = __shfl_sync(0xFFFFFFFFu, base, 31);
            int off = (int)base + scan - nr;
            #pragma unroll
            for (int k = 0; k < 4; k++) {
                if (((packed_border >> (8 * k)) & 0xFFu) == 0u)
                    g_rare[off++] = gbase + k;
            }
        }
    }

    // block reduction -> atomicAdd
    #pragma unroll
    for (int o = 16; o > 0; o >>= 1)
        nll += __shfl_down_sync(0xFFFFFFFFu, nll, o);
    __shared__ float ws[8];
    if (lane == 0) ws[wid] = nll;
    __syncthreads();
    if (wid == 0) {
        float v2 = (lane < (blockDim.x >> 5)) ? ws[lane] : 0.0f;
        #pragma unroll
        for (int o = 4; o > 0; o >>= 1)
            v2 += __shfl_down_sync(0xFFFFFFFFu, v2, o);
        if (lane == 0) atomicAdd(&g_ce, v2);
    }
}

// ---------------------------------------------------------------------------
// Kernel 2: border loss over the compacted candidate list (~31k px).
// Branch-free batched loads: 3 pred bytes + 8 ring-1 border bytes issued
// together (clamped addresses, 0/1 validity masks) -> ONE L2 round trip for
// the d=1 case, which is essentially all of them (P(d>=2) ~ 0.026^8).
// Exact expanding-ring fallback from tt=2. LAST BLOCK finalizes + resets.
// ---------------------------------------------------------------------------
__global__ void __launch_bounds__(DT_THREADS) dt_kernel(float* __restrict__ out) {
    __shared__ int wsum[DT_THREADS / 32];

    int n = (int)g_nrare;
    int contrib = 0;
    for (int it = blockIdx.x * blockDim.x + threadIdx.x; it < n;
         it += gridDim.x * blockDim.x) {
        int pix = g_rare[it];
        int b = pix / HWn;
        int hwv = pix - b * HWn;
        int gi = hwv / Wn;
        int gj = hwv - gi * Wn;
        const unsigned char* tb = g_tb + b * HWn;

        int hasU = (gi > 0), hasD = (gi < Hn - 1);
        int hasL = (gj > 0), hasR = (gj < Wn - 1);

        // --- batched independent loads (single round trip) ---
        int p0 = g_pred[pix];
        int pr = g_pred[pix + hasR];
        int pd = g_pred[pix + hasD * Wn];
        int cu = hwv - hasU * Wn, cd = hwv + hasD * Wn;
        int f = 0;
        f |= (int)tb[cu - hasL] & (hasU & hasL);
        f |= (int)tb[cu]        &  hasU;
        f |= (int)tb[cu + hasR] & (hasU & hasR);
        f |= (int)tb[hwv - hasL] & hasL;
        f |= (int)tb[hwv + hasR] & hasR;
        f |= (int)tb[cd - hasL] & (hasD & hasL);
        f |= (int)tb[cd]        &  hasD;
        f |= (int)tb[cd + hasR] & (hasD & hasR);

        bool pb = (((pd - p0) + (pr - p0)) != 0);
        if (!pb) continue;

        int d;
        if (f) {
            d = 1;
        } else {
            // exact expanding-ring Chebyshev fallback (essentially never taken)
            d = BOUND;
            for (int tt = 2; tt <= Hn + Wn; tt++) {
                bool g = false;
                int ra = gi - tt, rb = gi + tt;
                int ca = gj - tt, cb = gj + tt;
                int cl = ca > 0 ? ca : 0;
                int cr = cb < Wn - 1 ? cb : Wn - 1;
                if (ra >= 0) for (int c = cl; c <= cr; c++) g |= tb[ra * Wn + c] != 0;
                if (rb < Hn) for (int c = cl; c <= cr; c++) g |= tb[rb * Wn + c] != 0;
                int rl = (ra + 1) > 0 ? (ra + 1) : 0;
                int rh = (rb - 1) < Hn - 1 ? (rb - 1) : Hn - 1;
                if (ca >= 0) for (int r = rl; r <= rh; r++) g |= tb[r * Wn + ca] != 0;
                if (cb < Wn) for (int r = rl; r <= rh; r++) g |= tb[r * Wn + cb] != 0;
                if (g) { d = tt; break; }
                if (ra < 0 && rb >= Hn && ca < 0 && cb >= Wn) break;  // no border at all
            }
        }
        contrib += d;
    }

    // integer block reduction (exact) -> u32 atomic
    #pragma unroll
    for (int o = 16; o > 0; o >>= 1)
        contrib += __shfl_down_sync(0xFFFFFFFFu, contrib, o);
    int lane = threadIdx.x & 31, wid = threadIdx.x >> 5;
    if (lane == 0) wsum[wid] = contrib;
    __syncthreads();
    if (wid == 0) {
        int v2 = (lane < (DT_THREADS / 32)) ? wsum[lane] : 0;
        #pragma unroll
        for (int o = 4; o > 0; o >>= 1)
            v2 += __shfl_down_sync(0xFFFFFFFFu, v2, o);
        if (lane == 0) {
            atomicAdd(&g_border, (unsigned int)v2);
            __threadfence();
            unsigned int done = atomicAdd(&g_cnt, 1u);
            if (done == gridDim.x - 1) {       // last block: finalize + reset
                __threadfence();
                out[0] = g_ce + 0.2f * (float)g_border;
                g_ce = 0.0f;
                g_border = 0u;
                g_cnt = 0u;
                g_nrare = 0u;
            }
        }
    }
}

extern "C" void kernel_launch(void* const* d_in, const int* in_sizes, int n_in,
                              void* d_out, int out_size) {
    const float* slices  = (const float*)d_in[0];
    const int*   targets = (const int*)d_in[1];   // JAX int64 -> int32 (x64 disabled)
    float* out = (float*)d_out;

    ce_kernel<<<(NPIX / 4) / 256, 256>>>(slices, targets);
    dt_kernel<<<DT_GRID, DT_THREADS>>>(out);
}